// round 8
// baseline (speedup 1.0000x reference)
#include <cuda_runtime.h>
#include <math.h>

// Two-pass formulation.
// Pass 1 (pure stream): v[i,j] = b[i,j]*nr[j] for ALL i,j, row-major order.
// Pass 2 (L2-resident): lower triangle v[i,j] *= (1 - v[j,i]); diagonal = 0.
//   out (16MB) fits in L2 (126MB) and persists across launches.

#define TILE 32

// ---------------- Kernel 1: streaming v ----------------
__global__ __launch_bounds__(256) void dag_stream_kernel(
    const float4* __restrict__ rootp4,  // (n/4)
    const float4* __restrict__ edgep4,  // (n*n/4)
    const float4* __restrict__ groot4,  // (n/2)  float4 = 2 nodes
    const float4* __restrict__ gedge4,  // (n*n/2) float4 = 2 elements
    float4*       __restrict__ out4,    // (n*n/4)
    int n)
{
    const int gid  = blockIdx.x * 256 + threadIdx.x;   // float4 group id
    const int ng4  = n >> 2;                            // groups per row
    const int colg = gid & (ng4 - 1);                   // column group

    // Streams (DRAM):
    float4 e  = edgep4[gid];
    float4 g0 = gedge4[(long)gid * 2];
    float4 g1 = gedge4[(long)gid * 2 + 1];
    // Root data (L2-hot, 24KB total):
    float4 rp  = rootp4[colg];
    float4 gr0 = groot4[colg * 2];
    float4 gr1 = groot4[colg * 2 + 1];

    float nr0 = ((rp.x + gr0.x) > (1.0f - rp.x + gr0.y)) ? 0.0f : 1.0f;
    float nr1 = ((rp.y + gr0.z) > (1.0f - rp.y + gr0.w)) ? 0.0f : 1.0f;
    float nr2 = ((rp.z + gr1.x) > (1.0f - rp.z + gr1.y)) ? 0.0f : 1.0f;
    float nr3 = ((rp.w + gr1.z) > (1.0f - rp.w + gr1.w)) ? 0.0f : 1.0f;

    float4 v;
    v.x = (((e.x + g0.x) > (1.0f - e.x + g0.y)) ? 1.0f : 0.0f) * nr0;
    v.y = (((e.y + g0.z) > (1.0f - e.y + g0.w)) ? 1.0f : 0.0f) * nr1;
    v.z = (((e.z + g1.x) > (1.0f - e.z + g1.y)) ? 1.0f : 0.0f) * nr2;
    v.w = (((e.w + g1.z) > (1.0f - e.w + g1.w)) ? 1.0f : 0.0f) * nr3;

    out4[gid] = v;
}

// ---------------- Kernel 2: lower-triangle + diag fixup (L2) ----------------
__device__ __forceinline__ int low_row(int idx) {
    // strictly-lower pairs (bi > bj): idx = bi*(bi-1)/2 + bj
    double s = sqrt(1.0 + 8.0 * (double)idx);
    int bi = (int)((1.0 + s) * 0.5);
    if ((bi * (bi - 1)) / 2 > idx) bi--;
    else if (((bi + 1) * bi) / 2 <= idx) bi++;
    return bi;
}

__global__ __launch_bounds__(256) void dag_fix_kernel(
    float4* __restrict__ out4,
    int n, int T)
{
    const int bid = blockIdx.x;
    int bi, bj;
    if (bid < T) { bi = bid; bj = bid; }                 // diag tiles
    else {
        int idx = bid - T;
        bi = low_row(idx);
        bj = idx - (bi * (bi - 1)) / 2;                  // bj < bi
    }

    const int tid = threadIdx.x;
    const int lr  = tid >> 3;          // 0..31
    const int cg  = tid & 7;           // 0..7
    const int c4  = cg << 2;
    const int n4  = n >> 2;

    __shared__ float vP[TILE][TILE + 1];

    if (bi != bj) {
        // P tile = out(bj, bi) (upper, final values). Q tile = out(bi, bj).
        float4 p4 = out4[(long)(bj * TILE + lr) * n4 + bi * 8 + cg];
        long qidx = (long)(bi * TILE + lr) * n4 + bj * 8 + cg;
        float4 q4 = out4[qidx];
        vP[lr][c4 + 0] = p4.x;
        vP[lr][c4 + 1] = p4.y;
        vP[lr][c4 + 2] = p4.z;
        vP[lr][c4 + 3] = p4.w;
        __syncthreads();
        float4 o;
        o.x = q4.x * (1.0f - vP[c4 + 0][lr]);
        o.y = q4.y * (1.0f - vP[c4 + 1][lr]);
        o.z = q4.z * (1.0f - vP[c4 + 2][lr]);
        o.w = q4.w * (1.0f - vP[c4 + 3][lr]);
        out4[qidx] = o;
    } else {
        // Diagonal tile: lower-within-tile fix + zero diagonal.
        long idx = (long)(bi * TILE + lr) * n4 + bi * 8 + cg;
        float4 v4 = out4[idx];
        vP[lr][c4 + 0] = v4.x;
        vP[lr][c4 + 1] = v4.y;
        vP[lr][c4 + 2] = v4.z;
        vP[lr][c4 + 3] = v4.w;
        __syncthreads();
        float o[4] = {v4.x, v4.y, v4.z, v4.w};
        #pragma unroll
        for (int k = 0; k < 4; k++) {
            int cc = c4 + k;
            if (cc < lr)       o[k] = o[k] * (1.0f - vP[cc][lr]);
            else if (cc == lr) o[k] = 0.0f;
        }
        out4[idx] = make_float4(o[0], o[1], o[2], o[3]);
    }
}

extern "C" void kernel_launch(void* const* d_in, const int* in_sizes, int n_in,
                              void* d_out, int out_size) {
    const float4* rootp4 = (const float4*)d_in[0];
    const float4* edgep4 = (const float4*)d_in[1];
    const float4* groot4 = (const float4*)d_in[2];
    const float4* gedge4 = (const float4*)d_in[3];
    float4* out = (float4*)d_out;
    int n = in_sizes[0];
    int T = n / TILE;

    int ngroups = (n / 4) * n;
    dag_stream_kernel<<<ngroups / 256, 256>>>(rootp4, edgep4, groot4, gedge4, out, n);

    int nblk2 = T + T * (T - 1) / 2;   // diag tiles + strictly-lower tiles
    dag_fix_kernel<<<nblk2, 256>>>(out, n, T);
}